// round 6
// baseline (speedup 1.0000x reference)
#include <cuda_runtime.h>
#include <math.h>

#ifndef M_PI
#define M_PI 3.14159265358979323846
#endif

namespace {

constexpr int NP = 6;
constexpr int NWARP = 8;
constexpr int NTHR = NWARP * 32;

typedef unsigned long long u64;

// pair index tables packed as nibbles: entry t at bits [4t,4t+4)
__device__ constexpr u64 CI_PACK = 0x0433222111100000ull;
__device__ constexpr u64 CJ_PACK = 0x0554543543254321ull;

// rank-3 factor of F_ud: F_ud = sum_c g_L[c] g_L[c]^T
__device__ float g_L[3][64];

struct __align__(16) Smem {
  float4 F4[2][32][32];          // [m][k2][l] = (F[2k2][l],F[2k2][l+32],F[2k2+1][l],F[2k2+1][l+32])
  float2 phis2[NWARP][NP][64];   // duplicated: phis2[..][k] = (phi_k, phi_k)
  float  W1s[4 * 32];            // row-major [in][out]; consecutive pair = packed u64
  float  W2s[32 * 32];           // row-major [in][out]
  float  b1s[32], b2s[32], W3ss[32];
  float  xs[NWARP][NP][2];
  float  b3s, scale_s;
};

__device__ __forceinline__ u64 pk2(float a, float b) {
  u64 r; asm("mov.b64 %0, {%1, %2};" : "=l"(r) : "f"(a), "f"(b)); return r;
}
__device__ __forceinline__ void upk2(float& a, float& b, u64 v) {
  asm("mov.b64 {%0, %1}, %2;" : "=f"(a), "=f"(b) : "l"(v));
}
__device__ __forceinline__ void fma2(u64& d, u64 a, u64 b) {
  asm("fma.rn.f32x2 %0, %1, %2, %3;" : "=l"(d) : "l"(a), "l"(b), "l"(d));
}
__device__ __forceinline__ float hdot2(u64 a, u64 b) {
  u64 p; asm("mul.rn.f32x2 %0, %1, %2;" : "=l"(p) : "l"(a), "l"(b));
  float lo, hi; upk2(lo, hi, p);
  return lo + hi;
}
__device__ __forceinline__ float silu_f(float x) {
  float t;
  asm("tanh.approx.f32 %0, %1;" : "=f"(t) : "f"(x * 0.5f));
  return 0.5f * x * (1.0f + t);
}

// ---------- pre-kernel: pivoted rank-3 Cholesky of F_ud ----------
__global__ void factor_kernel(const float* __restrict__ F_ud) {
  __shared__ float diag[64];
  __shared__ float Lc[3][64];
  __shared__ int pivs;
  const int tid = threadIdx.x;  // 64 threads
  diag[tid] = F_ud[tid * 64 + tid];
  __syncthreads();
  for (int r = 0; r < 3; r++) {
    if (tid == 0) {
      int p = 0; float best = diag[0];
      for (int q = 1; q < 64; q++) if (diag[q] > best) { best = diag[q]; p = q; }
      pivs = p;
    }
    __syncthreads();
    const int p = pivs;
    float dp = diag[p];
    float col = F_ud[tid * 64 + p];
    for (int rp = 0; rp < r; rp++) col -= Lc[rp][tid] * Lc[rp][p];
    float inv = (dp > 1e-20f) ? (float)(1.0 / sqrt((double)dp)) : 0.f;
    float Lv = col * inv;
    __syncthreads();  // all reads of Lc/diag done
    Lc[r][tid] = Lv;
    diag[tid] -= Lv * Lv;
    __syncthreads();
  }
  for (int r = 0; r < 3; r++) g_L[r][tid] = Lc[r][tid];
}

// ---------- main kernel ----------
__global__ void __launch_bounds__(NTHR, 2)
pfaffian_kernel(const float* __restrict__ x, const int* __restrict__ spin,
                const float* __restrict__ F_uu, const float* __restrict__ F_dd,
                const float* __restrict__ W1, const float* __restrict__ b1,
                const float* __restrict__ W2, const float* __restrict__ b2,
                const float* __restrict__ W3, const float* __restrict__ b3,
                const float* __restrict__ scale,
                float* __restrict__ out, int Bt) {
  extern __shared__ char smem_raw[];
  Smem* S = reinterpret_cast<Smem*>(smem_raw);
  const int tid = threadIdx.x;
  const int w = tid >> 5, lane = tid & 31;

  // ---- stage antisymmetrized F_uu / F_dd (pair-packed) ----
  for (int idx = tid; idx < 2 * 32 * 32; idx += NTHR) {
    int m = idx >> 10, r = idx & 1023, k2 = r >> 5, l = r & 31;
    int k = 2 * k2;
    const float* F = m ? F_dd : F_uu;
    float4 v;
    v.x = F[k * 64 + l]            - F[l * 64 + k];
    v.y = F[k * 64 + l + 32]       - F[(l + 32) * 64 + k];
    v.z = F[(k + 1) * 64 + l]      - F[l * 64 + k + 1];
    v.w = F[(k + 1) * 64 + l + 32] - F[(l + 32) * 64 + k + 1];
    S->F4[m][k2][l] = v;
  }
  // ---- stage MLP weights verbatim (row-major; packed pairs are contiguous) ----
  for (int idx = tid; idx < 128; idx += NTHR) S->W1s[idx] = W1[idx];
  for (int idx = tid; idx < 1024; idx += NTHR) S->W2s[idx] = W2[idx];
  if (tid < 32) {
    S->b1s[tid] = b1[tid];
    S->b2s[tid] = b2[tid];
    S->W3ss[tid] = W3[tid];
  }
  if (tid == 0) { S->b3s = b3[0]; S->scale_s = scale[0]; }
  __syncthreads();

  // ---- per-lane basis norm constants ----
  const int nx1 = lane >> 3, nyi = lane & 7;
  float nA = 0.f, nB = 0.f, nC = 0.f;
  {
    double spi = sqrt(M_PI);
    double d = 1.0;
    for (int m2 = 0; m2 < 8; m2++) {
      float v = (float)(1.0 / sqrt(d * spi));
      if (m2 == nx1) nA = v;
      if (m2 == nx1 + 4) nB = v;
      if (m2 == nyi) nC = v;
      d *= 2.0 * (m2 + 1);
    }
  }
  const float norm1 = nA * nC, norm2 = nB * nC;
  const float scl = S->scale_s, b3v = S->b3s;

  // rank-3 factor columns for this lane's two basis cols
  u64 Lpk[3];
#pragma unroll
  for (int c = 0; c < 3; c++) Lpk[c] = pk2(g_L[c][lane], g_L[c][lane + 32]);

  const int ngroups = (Bt + NWARP - 1) / NWARP;
  for (int g = blockIdx.x; g < ngroups; g += gridDim.x) {
    const int e = g * NWARP + w;
    if (e >= Bt) continue;

    // ---- load x, spin ----
    int sval = 0;
    if (lane < NP) {
      float2 xv = *reinterpret_cast<const float2*>(x + (size_t)e * NP * 2 + lane * 2);
      S->xs[w][lane][0] = xv.x;
      S->xs[w][lane][1] = xv.y;
      sval = spin[(size_t)e * NP + lane];
    }
    unsigned mask = __ballot_sync(0xffffffffu, (lane < NP) && (sval == 1));
    __syncwarp();

    // ---- basis Phi ----
    float phiA[NP], phiB[NP];
#pragma unroll
    for (int p = 0; p < NP; p++) {
      float u = S->xs[w][p][0], v = S->xs[w][p][1];
      float hm = 1.f, h = 2.f * u;
      float hxa = (nx1 == 0) ? 1.f : h;
      float hxb = h;
#pragma unroll
      for (int k = 2; k < 8; k++) {
        float hn = fmaf(2.f * u, h, -2.f * (float)(k - 1) * hm);
        hm = h; h = hn;
        if (nx1 == k) hxa = hn;
        if (nx1 + 4 == k) hxb = hn;
      }
      float gm = 1.f, gh = 2.f * v;
      float hy = (nyi == 0) ? 1.f : gh;
#pragma unroll
      for (int k = 2; k < 8; k++) {
        float gn = fmaf(2.f * v, gh, -2.f * (float)(k - 1) * gm);
        gm = gh; gh = gn;
        if (nyi == k) hy = gn;
      }
      float gexp = __expf(-0.5f * (u * u + v * v));
      phiA[p] = hxa * hy * (norm1 * gexp);
      phiB[p] = hxb * hy * (norm2 * gexp);
      S->phis2[w][p][lane]      = make_float2(phiA[p], phiA[p]);
      S->phis2[w][p][lane + 32] = make_float2(phiB[p], phiB[p]);
    }
    __syncwarp();

    // ---- k-loop: uu + dd GEMVs, packed f32x2, zero-mov operand pairing ----
    u64 acc_uu[NP], acc_dd[NP];
#pragma unroll
    for (int p = 0; p < NP; p++) { acc_uu[p] = 0ull; acc_dd[p] = 0ull; }

#pragma unroll 8
    for (int k2 = 0; k2 < 32; k2++) {
      ulonglong2 fu = *reinterpret_cast<const ulonglong2*>(&S->F4[0][k2][lane]);
      ulonglong2 fd = *reinterpret_cast<const ulonglong2*>(&S->F4[1][k2][lane]);
#pragma unroll
      for (int p = 0; p < NP; p++) {
        ulonglong2 pv = *reinterpret_cast<const ulonglong2*>(&S->phis2[w][p][2 * k2]);
        fma2(acc_uu[p], pv.x, fu.x); fma2(acc_uu[p], pv.y, fu.y);
        fma2(acc_dd[p], pv.x, fd.x); fma2(acc_dd[p], pv.y, fd.y);
      }
    }

    // G_same select + packed phi
    u64 Gs[NP], phip[NP];
#pragma unroll
    for (int p = 0; p < NP; p++) {
      Gs[p] = ((mask >> p) & 1) ? acc_dd[p] : acc_uu[p];
      phip[p] = pk2(phiA[p], phiB[p]);
    }

    // ---- rank-3 projections t[p][c] = Phi_p . L_c (full sums on all lanes) ----
    float t18[18];
#pragma unroll
    for (int p = 0; p < NP; p++)
#pragma unroll
      for (int c = 0; c < 3; c++)
        t18[p * 3 + c] = hdot2(phip[p], Lpk[c]);
#pragma unroll
    for (int off = 16; off; off >>= 1)
#pragma unroll
      for (int q = 0; q < 18; q++)
        t18[q] += __shfl_xor_sync(0xffffffffu, t18[q], off);

    // ---- A base entries for 15 upper-tri pairs ----
    float abase = 0.f;
    {
      constexpr int PIc[15] = {0,0,0,0,0,1,1,1,1,2,2,2,3,3,4};
      constexpr int PJc[15] = {1,2,3,4,5,2,3,4,5,3,4,5,4,5,5};
#pragma unroll
      for (int t = 0; t < 15; t++) {
        const int i = PIc[t], j = PJc[t];
        int si = (mask >> i) & 1, sj = (mask >> j) & 1;
        float ds = hdot2(Gs[i], phip[j]);
#pragma unroll
        for (int off = 16; off; off >>= 1)
          ds += __shfl_xor_sync(0xffffffffu, ds, off);
        // A_ud[i][j] = t_i . t_j (symmetric under rank-3 factorization)
        float fv = t18[i * 3] * t18[j * 3]
                 + t18[i * 3 + 1] * t18[j * 3 + 1]
                 + t18[i * 3 + 2] * t18[j * 3 + 2];
        float val = (si == sj) ? ds : ((si == 0) ? fv : -fv);
        if (lane == t) abase = val;
      }
    }

    // ---- pair-correction MLP (packed f32x2, weights broadcast from smem) ----
    float finalA = 0.f;
    {
      int t = lane & 15;
      bool rev = lane >= 16;
      int pi = (int)((CI_PACK >> (4 * t)) & 15);
      int pj_ = (int)((CJ_PACK >> (4 * t)) & 15);
      int i = rev ? pj_ : pi;
      int j = rev ? pi : pj_;
      float f0 = S->xs[w][i][0] - S->xs[w][j][0];
      float f1 = S->xs[w][i][1] - S->xs[w][j][1];
      float f2v = f0 * f0 + f1 * f1;
      float f3 = (((mask >> i) & 1) == ((mask >> j) & 1)) ? 1.f : 0.f;

      u64 d0 = pk2(f0, f0), d1 = pk2(f1, f1), d2 = pk2(f2v, f2v), d3 = pk2(f3, f3);

      // layer 1: 32 neurons as 16 packed pairs
      float h1r[32];
#pragma unroll
      for (int o2 = 0; o2 < 16; o2++) {
        u64 acc = *reinterpret_cast<const u64*>(&S->b1s[2 * o2]);
        fma2(acc, d0, *reinterpret_cast<const u64*>(&S->W1s[0 * 32 + 2 * o2]));
        fma2(acc, d1, *reinterpret_cast<const u64*>(&S->W1s[1 * 32 + 2 * o2]));
        fma2(acc, d2, *reinterpret_cast<const u64*>(&S->W1s[2 * 32 + 2 * o2]));
        fma2(acc, d3, *reinterpret_cast<const u64*>(&S->W1s[3 * 32 + 2 * o2]));
        float s0, s1; upk2(s0, s1, acc);
        h1r[2 * o2] = silu_f(s0);
        h1r[2 * o2 + 1] = silu_f(s1);
      }

      // layer 2: 32x32 packed, k outer so a 16B read covers 2 neuron-pairs
      u64 acc2[16];
#pragma unroll
      for (int o2 = 0; o2 < 16; o2++)
        acc2[o2] = *reinterpret_cast<const u64*>(&S->b2s[2 * o2]);
#pragma unroll 8
      for (int k = 0; k < 32; k++) {
        u64 hk = pk2(h1r[k], h1r[k]);
#pragma unroll
        for (int q = 0; q < 8; q++) {
          ulonglong2 wv = *reinterpret_cast<const ulonglong2*>(&S->W2s[k * 32 + 4 * q]);
          fma2(acc2[2 * q], hk, wv.x);
          fma2(acc2[2 * q + 1], hk, wv.y);
        }
      }

      // layer 3
      u64 oacc = 0ull;
#pragma unroll
      for (int o2 = 0; o2 < 16; o2++) {
        float s0, s1; upk2(s0, s1, acc2[o2]);
        u64 sp = pk2(silu_f(s0), silu_f(s1));
        fma2(oacc, sp, *reinterpret_cast<const u64*>(&S->W3ss[2 * o2]));
      }
      float o0, o1; upk2(o0, o1, oacc);
      float outv = b3v + o0 + o1;

      float orev = __shfl_down_sync(0xffffffffu, outv, 16);
      finalA = abase + scl * (outv - orev);  // valid on lanes 0..14
    }

    // ---- gather A via shfl, Pfaffian ----
    {
      float a0  = __shfl_sync(0xffffffffu, finalA, 0);
      float a1  = __shfl_sync(0xffffffffu, finalA, 1);
      float a2  = __shfl_sync(0xffffffffu, finalA, 2);
      float a3  = __shfl_sync(0xffffffffu, finalA, 3);
      float a4  = __shfl_sync(0xffffffffu, finalA, 4);
      float a5  = __shfl_sync(0xffffffffu, finalA, 5);
      float a6  = __shfl_sync(0xffffffffu, finalA, 6);
      float a7  = __shfl_sync(0xffffffffu, finalA, 7);
      float a8  = __shfl_sync(0xffffffffu, finalA, 8);
      float a9  = __shfl_sync(0xffffffffu, finalA, 9);
      float a10 = __shfl_sync(0xffffffffu, finalA, 10);
      float a11 = __shfl_sync(0xffffffffu, finalA, 11);
      float a12 = __shfl_sync(0xffffffffu, finalA, 12);
      float a13 = __shfl_sync(0xffffffffu, finalA, 13);
      float a14 = __shfl_sync(0xffffffffu, finalA, 14);
      if (lane == 0) {
        float pf = a0 * (a9 * a14 - a10 * a13 + a11 * a12)
                 - a1 * (a6 * a14 - a7 * a13 + a8 * a12)
                 + a2 * (a5 * a14 - a7 * a11 + a8 * a10)
                 - a3 * (a5 * a13 - a6 * a11 + a8 * a9)
                 + a4 * (a5 * a12 - a6 * a10 + a7 * a9);
        float sgn = (pf == 0.f) ? 1.f : ((pf > 0.f) ? 1.f : -1.f);
        float la = 0.5f * __logf(pf * pf);
        out[e] = sgn;
        out[Bt + e] = la;
      }
    }
    __syncwarp();
  }
}

}  // namespace

extern "C" void kernel_launch(void* const* d_in, const int* in_sizes, int n_in,
                              void* d_out, int out_size) {
  const float* x     = (const float*)d_in[0];
  const int*   spin  = (const int*)d_in[1];
  const float* F_ud  = (const float*)d_in[2];
  const float* F_uu  = (const float*)d_in[3];
  const float* F_dd  = (const float*)d_in[4];
  const float* W1    = (const float*)d_in[5];
  const float* b1    = (const float*)d_in[6];
  const float* W2    = (const float*)d_in[7];
  const float* b2    = (const float*)d_in[8];
  const float* W3    = (const float*)d_in[9];
  const float* b3    = (const float*)d_in[10];
  const float* scale = (const float*)d_in[11];
  float* out = (float*)d_out;

  const int Bt = in_sizes[0] / (NP * 2);
  const int smem = (int)sizeof(Smem);

  // rank-3 factorization of F_ud (plain kernel launch, graph-capturable)
  factor_kernel<<<1, 64>>>(F_ud);

  cudaFuncSetAttribute(pfaffian_kernel, cudaFuncAttributeMaxDynamicSharedMemorySize, smem);

  int dev = 0;
  cudaGetDevice(&dev);
  int nsm = 148;
  cudaDeviceGetAttribute(&nsm, cudaDevAttrMultiProcessorCount, dev);

  const int ngroups = (Bt + NWARP - 1) / NWARP;
  int grid = nsm * 2;
  if (grid > ngroups) grid = ngroups;

  pfaffian_kernel<<<grid, NTHR, smem>>>(x, spin, F_uu, F_dd,
                                        W1, b1, W2, b2, W3, b3, scale, out, Bt);
}